// round 14
// baseline (speedup 1.0000x reference)
#include <cuda_runtime.h>
#include <cuda_bf16.h>
#include <math.h>
#include <stdint.h>

// Problem constants (fixed by the reference)
#define B_   2
#define L_   1024
#define V_   50257
#define LP1_ (L_ + 1)
#define BETA_     0.04f
#define CLIP_LO_  0.8f   // 1 - EPS_LOW
#define CLIP_HI_  1.2f   // 1 + EPS_HIGH
#define NROWS_ (B_ * L_)
#define SEGS_  4                          // segments per row
#define NBLOCKS_ (NROWS_ * SEGS_)         // 8192 blocks, 98.8% wave util

#define DEPTH_      6                     // cp.async ring slots (4 KB each)
#define STAGE_F4_   256                   // one float4 per thread per stage
#define SLOT_B_     4096u
// Static schedule facts (hold for ALL rows/segments):
//   peel in [0,31] => n4 in [12556,12564] => chunk = 3144 f4 always.
//   Split per segment: 8 async stages (2048 f4) + 4 direct-LDG chunks
//   (1024 f4, region [2048,3072)) + partial rem = len-3072 in [52,72].
#define CHUNK_F4_   3144
#define A_F4_       2048                  // async-part float4s (8 stages)
#define B_OFF_      2048                  // direct-LDG region start (f4)

// Per-row partial LSE accumulators + tickets. Self-resetting each run
// (atomicInc wraps; last segment zeroes the sum) -> graph-replay safe.
__device__ float        g_row_sum[NROWS_];
__device__ unsigned int g_row_cnt[NROWS_];
// Global scalar accumulators: [0]=loss s0,[1]=loss s1,[2]=mask s0,[3]=mask s1,
// [4]=kl,[5]=clip. Reset by the last row-ticket holder.
__device__ float        g_acc[6];
__device__ unsigned int g_ticket;

static __device__ __forceinline__ uint32_t smem_u32(const void* p) {
    uint32_t a;
    asm("{ .reg .u64 t; cvta.to.shared.u64 t, %1; cvt.u32.u64 %0, t; }"
        : "=r"(a) : "l"(p));
    return a;
}

// 16-byte cp.async, L1-bypass (.cg): streaming read-once data.
static __device__ __forceinline__ void cp16(uint32_t dst, const void* src) {
    asm volatile("cp.async.cg.shared.global [%0], [%1], 16;"
                 :: "r"(dst), "l"(src) : "memory");
}
static __device__ __forceinline__ void cp_commit() {
    asm volatile("cp.async.commit_group;" ::: "memory");
}
template <int N>
static __device__ __forceinline__ void cp_wait() {
    asm volatile("cp.async.wait_group %0;" :: "n"(N) : "memory");
}

#define EXP4_(v) do {                       \
    s0 += __expf((v).x);  s1 += __expf((v).y); \
    s2 += __expf((v).z);  s3 += __expf((v).w); } while (0)

// ---------------------------------------------------------------------------
// Dual-path statically-scheduled streaming kernel: block (row, seg) covers
// 3144 f4. Path 1 (cp.async, L1-bypass): 8 stages of 256 f4 through a 6-slot
// smem ring. Path 2 (direct LDG.128): 4 chunks of 256 f4, double-buffered
// two stages ahead, consumed interleaved with stages 0-3. Both paths run
// concurrently, filling DRAM idle cycles that a single path leaves.
// Exact wait-group schedule (groups G0..G8): waits 5,5,5,5,4,3,2,1,0.
// No __syncthreads / mbarriers in the stream. Single-pass sum(exp)
// (logits ~ N(0,1), fp32-safe). Per-row combine via atomics; last segment
// does GRPO token math; last row writes the 3 outputs.
// ---------------------------------------------------------------------------
__global__ __launch_bounds__(256, 8) void grpo_dual_kernel(
    const float* __restrict__ logits,
    const int*   __restrict__ completion_ids,
    const float* __restrict__ advantages,
    const float* __restrict__ old_logp,
    const float* __restrict__ ref_logp,
    const int*   __restrict__ completion_mask,
    float*       __restrict__ out)
{
    __shared__ __align__(128) float4 sbuf[DEPTH_][STAGE_F4_];   // 24 KB
    __shared__ float warp_sums[8];

    const int row = blockIdx.x >> 2;         // SEGS_ = 4
    const int seg = blockIdx.x & (SEGS_ - 1);
    const int b   = row >> 10;               // L_ = 1024
    const int l   = row & (L_ - 1);
    const size_t base_elems = (size_t)(b * LP1_ + l) * V_;
    const float* __restrict__ x = logits + base_elems;
    const int tid = threadIdx.x;

    // ---- peel to a 128-byte (32-float) boundary; seg 0 handles it ----
    const int mis  = (int)(base_elems & 31);
    const int peel = (32 - mis) & 31;                 // 0..31 scalars
    const int n4   = (V_ - peel) >> 2;                // 12556..12564
    const float4* __restrict__ x4 = (const float4*)(x + peel);

    const int i0  = seg * CHUNK_F4_;
    const int i1e = i0 + CHUNK_F4_;
    const int i1  = (i1e < n4) ? i1e : n4;
    const int rem = (i1 - i0) - (B_OFF_ + 1024);      // 52..72, always > 0

    const uint32_t slot0 = smem_u32(&sbuf[0][tid]);
    const float4* gsrc = x4 + i0 + tid;               // async lane base
    const float4* gB   = gsrc + B_OFF_;               // direct-LDG lane base

    float s0 = 0.f, s1 = 0.f, s2 = 0.f, s3 = 0.f;
    if (seg == 0 && tid < peel) s0 += __expf(x[tid]);
    if (seg == SEGS_ - 1) {                  // scalar tail (<= 3 elements)
        const int ti = peel + (n4 << 2) + tid;
        if (ti < V_) s0 += __expf(x[ti]);
    }

    // ---- prologue: direct-LDG double buffer + async stages 0..5 ----
    float4 rb0 = gB[0];                      // B-chunk 0
    float4 rb1 = gB[256];                    // B-chunk 1
    #pragma unroll
    for (int k = 0; k < DEPTH_; ++k) {       // groups G0..G5
        cp16(slot0 + SLOT_B_ * k, (const void*)(gsrc + STAGE_F4_ * k));
        cp_commit();
    }

    // ---- static dual-path mainloop (stages = groups G0..G7, partial G8) --
    // k=0: consume G0 + B0; refill G6; prefetch B2
    cp_wait<5>();
    { const float4 v = sbuf[0][tid]; EXP4_(v); }
    EXP4_(rb0);
    rb0 = gB[512];
    cp16(slot0, (const void*)(gsrc + STAGE_F4_ * 6));  cp_commit();   // G6

    // k=1: consume G1 + B1; refill G7; prefetch B3
    cp_wait<5>();
    { const float4 v = sbuf[1][tid]; EXP4_(v); }
    EXP4_(rb1);
    rb1 = gB[768];
    cp16(slot0 + SLOT_B_, (const void*)(gsrc + STAGE_F4_ * 7)); cp_commit(); // G7

    // k=2: consume G2 + B2; issue partial G8 (slot 2 freed after consume)
    cp_wait<5>();
    { const float4 v = sbuf[2][tid]; EXP4_(v); }
    EXP4_(rb0);
    if (tid < rem)
        cp16(slot0 + SLOT_B_ * 2, (const void*)(gsrc + (B_OFF_ + 1024)));
    cp_commit();                                                       // G8

    // k=3: consume G3 + B3
    cp_wait<5>();
    { const float4 v = sbuf[3][tid]; EXP4_(v); }
    EXP4_(rb1);

    // k=4..7: consume G4..G7 (slots 4,5,0,1)
    cp_wait<4>();
    { const float4 v = sbuf[4][tid]; EXP4_(v); }
    cp_wait<3>();
    { const float4 v = sbuf[5][tid]; EXP4_(v); }
    cp_wait<2>();
    { const float4 v = sbuf[0][tid]; EXP4_(v); }
    cp_wait<1>();
    { const float4 v = sbuf[1][tid]; EXP4_(v); }

    // final: partial stage (G8, slot 2)
    cp_wait<0>();
    if (tid < rem) { const float4 v = sbuf[2][tid]; EXP4_(v); }

    float s = (s0 + s1) + (s2 + s3);

    // ---- block reduction (8 warps) ----
    #pragma unroll
    for (int off = 16; off > 0; off >>= 1)
        s += __shfl_down_sync(0xFFFFFFFFu, s, off);
    const int lane = tid & 31;
    const int wid  = tid >> 5;
    if (lane == 0) warp_sums[wid] = s;
    __syncthreads();

    if (tid == 0) {
        float part = 0.f;
        #pragma unroll
        for (int w = 0; w < 8; ++w) part += warp_sums[w];

        atomicAdd(&g_row_sum[row], part);
        __threadfence();
        const unsigned t = atomicInc(&g_row_cnt[row], SEGS_ - 1); // wraps to 0
        if (t == SEGS_ - 1) {
            __threadfence();
            const float tot = atomicAdd(&g_row_sum[row], 0.f);  // atomic read
            g_row_sum[row] = 0.f;                               // replay reset

            const int   cid = completion_ids[row];
            const float tok = __ldg(&x[cid]);
            const float lp  = tok - logf(tot);

            const float m = (float)completion_mask[row];
            const float a = advantages[b];

            const float coef1 = __expf(lp - old_logp[row]);
            const float coef2 = fminf(fmaxf(coef1, CLIP_LO_), CLIP_HI_);
            const float loss1 = coef1 * a;
            const float loss2 = coef2 * a;

            const float diff = ref_logp[row] - lp;
            const float kl   = __expf(diff) - diff - 1.f;

            const float ptl = -fminf(loss1, loss2) + BETA_ * kl;

            const bool clipped = (coef1 < CLIP_LO_ && a < 0.f) ||
                                 (coef1 > CLIP_HI_ && a > 0.f);

            atomicAdd(&g_acc[0 + b], ptl * m);
            atomicAdd(&g_acc[2 + b], m);
            atomicAdd(&g_acc[4],     kl * m);
            if (clipped) atomicAdd(&g_acc[5], m);

            __threadfence();
            const unsigned my_ticket = atomicInc(&g_ticket, NROWS_ - 1);
            if (my_ticket == NROWS_ - 1) {
                __threadfence();
                const float ls0 = g_acc[0], ls1 = g_acc[1];
                const float ms0 = g_acc[2], ms1 = g_acc[3];
                const float klS = g_acc[4], clS = g_acc[5];

                const float mask_total = fmaxf(ms0 + ms1, 1.f);
                out[0] = 0.5f * (ls0 / fmaxf(ms0, 1.f) +
                                 ls1 / fmaxf(ms1, 1.f));
                out[1] = klS / mask_total;
                out[2] = clS / mask_total;

                #pragma unroll
                for (int k2 = 0; k2 < 6; ++k2) g_acc[k2] = 0.f;
                __threadfence();
            }
        }
    }
}

// ---------------------------------------------------------------------------
// kernel_launch — metadata order:
//   0: logits (f32, B*(L+1)*V)   1: completion_ids (i32, B*L)
//   2: advantages (f32, B)       3: old_logp (f32, B*L)
//   4: ref_logp (f32, B*L)       5: completion_mask (i32, B*L)
// output: 3 f32 scalars (reduced_loss, kl_mean, clip_ratio)
// ---------------------------------------------------------------------------
extern "C" void kernel_launch(void* const* d_in, const int* in_sizes, int n_in,
                              void* d_out, int out_size)
{
    const float* logits          = (const float*)d_in[0];
    const int*   completion_ids  = (const int*)  d_in[1];
    const float* advantages      = (const float*)d_in[2];
    const float* old_logp        = (const float*)d_in[3];
    const float* ref_logp        = (const float*)d_in[4];
    const int*   completion_mask = (const int*)  d_in[5];
    float* out = (float*)d_out;

    grpo_dual_kernel<<<NBLOCKS_, 256>>>(logits, completion_ids, advantages,
                                        old_logp, ref_logp, completion_mask,
                                        out);
}

// round 15
// speedup vs baseline: 1.0015x; 1.0015x over previous
#include <cuda_runtime.h>
#include <cuda_bf16.h>
#include <math.h>
#include <stdint.h>

// Problem constants (fixed by the reference)
#define B_   2
#define L_   1024
#define V_   50257
#define LP1_ (L_ + 1)
#define BETA_     0.04f
#define CLIP_LO_  0.8f   // 1 - EPS_LOW
#define CLIP_HI_  1.2f   // 1 + EPS_HIGH
#define NROWS_ (B_ * L_)
#define SEGS_  4                          // segments per row
#define NBLOCKS_ (NROWS_ * SEGS_)         // 8192 blocks, 98.8% wave util

#define DEPTH_      6                     // cp.async ring slots (4 KB each)
#define STAGE_F4_   256                   // one float4 per thread per stage
#define SLOT_B_     4096u
// Static schedule facts (hold for ALL rows/segments):
//   peel in [0,31] => n4 in [12556,12564] => chunk = 3144 f4 always.
//   Split: 8 async stages (2048 f4) + LDG region [2048, len): 4 full chunks
//   (1024 f4) + partial rem = len-3072 in [52,72] (predicated LDG).
#define CHUNK_F4_   3144
#define B_OFF_      2048                  // direct-LDG region start (f4)

// Per-row partial LSE accumulators + tickets. Self-resetting each run
// (atomicInc wraps; last segment zeroes the sum) -> graph-replay safe.
__device__ float        g_row_sum[NROWS_];
__device__ unsigned int g_row_cnt[NROWS_];
// Global scalar accumulators: [0]=loss s0,[1]=loss s1,[2]=mask s0,[3]=mask s1,
// [4]=kl,[5]=clip. Reset by the last row-ticket holder.
__device__ float        g_acc[6];
__device__ unsigned int g_ticket;

static __device__ __forceinline__ uint32_t smem_u32(const void* p) {
    uint32_t a;
    asm("{ .reg .u64 t; cvta.to.shared.u64 t, %1; cvt.u32.u64 %0, t; }"
        : "=r"(a) : "l"(p));
    return a;
}

// 16-byte cp.async, L1-bypass (.cg): streaming read-once data.
static __device__ __forceinline__ void cp16(uint32_t dst, const void* src) {
    asm volatile("cp.async.cg.shared.global [%0], [%1], 16;"
                 :: "r"(dst), "l"(src) : "memory");
}
static __device__ __forceinline__ void cp_commit() {
    asm volatile("cp.async.commit_group;" ::: "memory");
}
template <int N>
static __device__ __forceinline__ void cp_wait() {
    asm volatile("cp.async.wait_group %0;" :: "n"(N) : "memory");
}

#define EXP4_(v) do {                       \
    s0 += __expf((v).x);  s1 += __expf((v).y); \
    s2 += __expf((v).z);  s3 += __expf((v).w); } while (0)

// ---------------------------------------------------------------------------
// Dual-path streaming kernel, BALANCED static schedule: block (row, seg)
// covers ~3144 f4.  Async path: 8 full stages (G0..G7) through a 6-slot smem
// ring, waits 5,5,5,4,3,2,1,0.  LDG path: 4 full chunks consumed at stages
// 0/2/4/6 + predicated partial consumed at stage 7, prefetched two stages
// ahead — LDG issues span the whole block, so both memory paths stay live
// concurrently ~90% of the time (R14 overlapped only the first half).
// No __syncthreads / mbarriers in the stream. Single-pass sum(exp)
// (logits ~ N(0,1), fp32-safe). Per-row combine via atomics; last segment
// does GRPO token math; last row writes the 3 outputs.
// ---------------------------------------------------------------------------
__global__ __launch_bounds__(256, 8) void grpo_dual_kernel(
    const float* __restrict__ logits,
    const int*   __restrict__ completion_ids,
    const float* __restrict__ advantages,
    const float* __restrict__ old_logp,
    const float* __restrict__ ref_logp,
    const int*   __restrict__ completion_mask,
    float*       __restrict__ out)
{
    __shared__ __align__(128) float4 sbuf[DEPTH_][STAGE_F4_];   // 24 KB
    __shared__ float warp_sums[8];

    const int row = blockIdx.x >> 2;         // SEGS_ = 4
    const int seg = blockIdx.x & (SEGS_ - 1);
    const int b   = row >> 10;               // L_ = 1024
    const int l   = row & (L_ - 1);
    const size_t base_elems = (size_t)(b * LP1_ + l) * V_;
    const float* __restrict__ x = logits + base_elems;
    const int tid = threadIdx.x;

    // ---- peel to a 128-byte (32-float) boundary; seg 0 handles it ----
    const int mis  = (int)(base_elems & 31);
    const int peel = (32 - mis) & 31;                 // 0..31 scalars
    const int n4   = (V_ - peel) >> 2;                // 12556..12564
    const float4* __restrict__ x4 = (const float4*)(x + peel);

    const int i0  = seg * CHUNK_F4_;
    const int i1e = i0 + CHUNK_F4_;
    const int i1  = (i1e < n4) ? i1e : n4;
    const int rem = (i1 - i0) - (B_OFF_ + 1024);      // 52..72, always > 0

    const uint32_t slot0 = smem_u32(&sbuf[0][tid]);
    const float4* gsrc = x4 + i0 + tid;               // async lane base
    const float4* gB   = gsrc + B_OFF_;               // direct-LDG lane base

    float s0 = 0.f, s1 = 0.f, s2 = 0.f, s3 = 0.f;
    if (seg == 0 && tid < peel) s0 += __expf(x[tid]);
    if (seg == SEGS_ - 1) {                  // scalar tail (<= 3 elements)
        const int ti = peel + (n4 << 2) + tid;
        if (ti < V_) s0 += __expf(x[ti]);
    }

    // ---- prologue: LDG double buffer (B0,B1) + async stages 0..5 ----
    float4 rb0 = gB[0];                      // B-chunk 0 (consume @ stage 0)
    float4 rb1 = gB[256];                    // B-chunk 1 (consume @ stage 2)
    #pragma unroll
    for (int k = 0; k < DEPTH_; ++k) {       // groups G0..G5
        cp16(slot0 + SLOT_B_ * k, (const void*)(gsrc + STAGE_F4_ * k));
        cp_commit();
    }

    // ---- balanced dual-path mainloop (async G0..G7; LDG @ 0/2/4/6/7) ----
    // stage 0: async G0 + LDG B0; prefetch B2; refill G6
    cp_wait<5>();
    { const float4 v = sbuf[0][tid]; EXP4_(v); }
    EXP4_(rb0);
    rb0 = gB[512];                                        // B2
    cp16(slot0, (const void*)(gsrc + STAGE_F4_ * 6));  cp_commit();   // G6

    // stage 1: async G1; refill G7
    cp_wait<5>();
    { const float4 v = sbuf[1][tid]; EXP4_(v); }
    cp16(slot0 + SLOT_B_, (const void*)(gsrc + STAGE_F4_ * 7)); cp_commit(); // G7

    // stage 2: async G2 + LDG B1; prefetch B3
    cp_wait<5>();
    { const float4 v = sbuf[2][tid]; EXP4_(v); }
    EXP4_(rb1);
    rb1 = gB[768];                                        // B3

    // stage 3: async G3
    cp_wait<4>();
    { const float4 v = sbuf[3][tid]; EXP4_(v); }

    // stage 4: async G4 + LDG B2; prefetch partial (predicated)
    cp_wait<3>();
    { const float4 v = sbuf[4][tid]; EXP4_(v); }
    EXP4_(rb0);
    float4 rbp;
    if (tid < rem) rbp = gB[1024];                        // partial chunk

    // stage 5: async G5
    cp_wait<2>();
    { const float4 v = sbuf[5][tid]; EXP4_(v); }

    // stage 6: async G6 (slot 0) + LDG B3
    cp_wait<1>();
    { const float4 v = sbuf[0][tid]; EXP4_(v); }
    EXP4_(rb1);

    // stage 7: async G7 (slot 1) + partial LDG
    cp_wait<0>();
    { const float4 v = sbuf[1][tid]; EXP4_(v); }
    if (tid < rem) { EXP4_(rbp); }

    float s = (s0 + s1) + (s2 + s3);

    // ---- block reduction (8 warps) ----
    #pragma unroll
    for (int off = 16; off > 0; off >>= 1)
        s += __shfl_down_sync(0xFFFFFFFFu, s, off);
    const int lane = tid & 31;
    const int wid  = tid >> 5;
    if (lane == 0) warp_sums[wid] = s;
    __syncthreads();

    if (tid == 0) {
        float part = 0.f;
        #pragma unroll
        for (int w = 0; w < 8; ++w) part += warp_sums[w];

        atomicAdd(&g_row_sum[row], part);
        __threadfence();
        const unsigned t = atomicInc(&g_row_cnt[row], SEGS_ - 1); // wraps to 0
        if (t == SEGS_ - 1) {
            __threadfence();
            const float tot = atomicAdd(&g_row_sum[row], 0.f);  // atomic read
            g_row_sum[row] = 0.f;                               // replay reset

            const int   cid = completion_ids[row];
            const float tok = __ldg(&x[cid]);
            const float lp  = tok - logf(tot);

            const float m = (float)completion_mask[row];
            const float a = advantages[b];

            const float coef1 = __expf(lp - old_logp[row]);
            const float coef2 = fminf(fmaxf(coef1, CLIP_LO_), CLIP_HI_);
            const float loss1 = coef1 * a;
            const float loss2 = coef2 * a;

            const float diff = ref_logp[row] - lp;
            const float kl   = __expf(diff) - diff - 1.f;

            const float ptl = -fminf(loss1, loss2) + BETA_ * kl;

            const bool clipped = (coef1 < CLIP_LO_ && a < 0.f) ||
                                 (coef1 > CLIP_HI_ && a > 0.f);

            atomicAdd(&g_acc[0 + b], ptl * m);
            atomicAdd(&g_acc[2 + b], m);
            atomicAdd(&g_acc[4],     kl * m);
            if (clipped) atomicAdd(&g_acc[5], m);

            __threadfence();
            const unsigned my_ticket = atomicInc(&g_ticket, NROWS_ - 1);
            if (my_ticket == NROWS_ - 1) {
                __threadfence();
                const float ls0 = g_acc[0], ls1 = g_acc[1];
                const float ms0 = g_acc[2], ms1 = g_acc[3];
                const float klS = g_acc[4], clS = g_acc[5];

                const float mask_total = fmaxf(ms0 + ms1, 1.f);
                out[0] = 0.5f * (ls0 / fmaxf(ms0, 1.f) +
                                 ls1 / fmaxf(ms1, 1.f));
                out[1] = klS / mask_total;
                out[2] = clS / mask_total;

                #pragma unroll
                for (int k2 = 0; k2 < 6; ++k2) g_acc[k2] = 0.f;
                __threadfence();
            }
        }
    }
}

// ---------------------------------------------------------------------------
// kernel_launch — metadata order:
//   0: logits (f32, B*(L+1)*V)   1: completion_ids (i32, B*L)
//   2: advantages (f32, B)       3: old_logp (f32, B*L)
//   4: ref_logp (f32, B*L)       5: completion_mask (i32, B*L)
// output: 3 f32 scalars (reduced_loss, kl_mean, clip_ratio)
// ---------------------------------------------------------------------------
extern "C" void kernel_launch(void* const* d_in, const int* in_sizes, int n_in,
                              void* d_out, int out_size)
{
    const float* logits          = (const float*)d_in[0];
    const int*   completion_ids  = (const int*)  d_in[1];
    const float* advantages      = (const float*)d_in[2];
    const float* old_logp        = (const float*)d_in[3];
    const float* ref_logp        = (const float*)d_in[4];
    const int*   completion_mask = (const int*)  d_in[5];
    float* out = (float*)d_out;

    grpo_dual_kernel<<<NBLOCKS_, 256>>>(logits, completion_ids, advantages,
                                        old_logp, ref_logp, completion_mask,
                                        out);
}